// round 15
// baseline (speedup 1.0000x reference)
#include <cuda_runtime.h>

// Problem constants: H=64, M=N=128, k=9, w=3
#define PTOT (64 * 128 * 128)
#define KNN  9

// ---- pass1 tile: 16 x 4 x 4; halo 18 x 6 x 6 ----
#define TX 16
#define TY 4
#define TZ 4
#define HX 18
#define HY 6
#define HROWS (HX * HY * 6)     // 648
#define HXY (HX * HY)           // 108

// ---- pass2 tile: 16 x 8 x 4, 512 threads; value-row halo 18 x 10 x 6 ----
#define H2X 18
#define H2XY (18 * 10)          // 180
#define H2ROWS (18 * 10 * 6)    // 1080
#define ROWP 10                 // padded row width (floats): 40 B, 8B-aligned
// pass2 anat halo: 20 x 12 x 8
#define A2X 20
#define A2XY 240
#define A2ROWS (A2X * 12 * 8)   // 1920
#define SMEM2_BYTES ((H2ROWS * ROWP + A2ROWS) * 4)  // 43200 + 7680 = 50880 B

// Scratch: ONLY codes — one uint4 per voxel, 9 code bytes in .x/.y/.z
// (byte = (oz<<4)|(oy<<2)|ox, offsets in 0..2), .w unused. 16.8 MB.
__device__ uint4 g_code4[PTOT];

// ---------------------------------------------------------------------------
// Pass 1 (exact R14 version — measured ~62us): stable top-9 of 27 periodic
// window neighbors by |v - center| via branchless byte-packed rank counting.
// ---------------------------------------------------------------------------
__global__ __launch_bounds__(256) void pass1_kernel(const float* __restrict__ anat) {
    __shared__ float s_anat[HROWS];
    __shared__ unsigned char s_cb[256 * 20];

    int tid = threadIdx.x;
    int lx = tid & 15, ly = (tid >> 4) & 3, lz = tid >> 6;
    int x0 = blockIdx.x * TX, y0 = blockIdx.y * TY, z0 = blockIdx.z * TZ;

    for (int t = tid; t < HROWS; t += 256) {
        int hx = t % HX; int r = t / HX; int hy = r % HY; int hz = r / HY;
        int gx = (x0 + hx + 127) & 127;
        int gy = (y0 + hy + 127) & 127;
        int gz = (z0 + hz + 63) & 63;
        s_anat[t] = __ldg(&anat[(gz << 14) | (gy << 7) | gx]);
    }
    __syncthreads();

    int center = (lz + 1) * HXY + (ly + 1) * HX + (lx + 1);
    float ac = s_anat[center];

    int di[27];
#pragma unroll
    for (int oz = 0; oz < 3; ++oz)
#pragma unroll
        for (int oy = 0; oy < 3; ++oy)
#pragma unroll
            for (int ox = 0; ox < 3; ++ox) {
                int c = oz * 9 + oy * 3 + ox;
                float v = s_anat[center + (oz - 1) * HXY + (oy - 1) * HX + (ox - 1)];
                di[c] = (int)(__float_as_uint(v - ac) & 0x7fffffffu);
            }

    unsigned ri[7] = { 0x03020100u, 0x07060504u, 0x0B0A0908u, 0x0F0E0D0Cu,
                       0x13121110u, 0x17161514u, 0x001A1918u };

#pragma unroll
    for (int j = 0; j < 13; ++j) {
        unsigned p = ((unsigned)(-di[j])) >> 31;
        ri[j >> 2] += p * (1u << ((j & 3) * 8));
        ri[3]      -= p * (1u << 8);
    }

#pragma unroll
    for (int o = 1; o < 27; ++o)
#pragma unroll
        for (int j = 0; j + o < 27; ++j) {
            const int c = j + o;
            if (j == 13 || c == 13) continue;
            unsigned p = ((unsigned)(di[c] - di[j])) >> 31;   // d_j > d_c
            ri[j >> 2] += p * (1u << ((j & 3) * 8));
            ri[c >> 2] -= p * (1u << ((c & 3) * 8));
        }

    unsigned char* myrow = &s_cb[tid * 20];
#pragma unroll
    for (int c = 0; c < 27; ++c) {
        int r = (int)((ri[c >> 2] >> ((c & 3) * 8)) & 255u);
        if (r < KNN) {
            int oz = c / 9, rem = c - 9 * oz, oy = rem / 3, ox = rem - 3 * oy; // compile-time
            myrow[r] = (unsigned char)((oz << 4) | (oy << 2) | ox);
        }
    }
    unsigned w0 = *(const unsigned*)&myrow[0];
    unsigned w1 = *(const unsigned*)&myrow[4];
    unsigned w2 = (unsigned)myrow[8];
    int i = ((z0 + lz) << 14) | ((y0 + ly) << 7) | (x0 + lx);
    g_code4[i] = make_uint4(w0, w1, w2, 0u);
}

// ---------------------------------------------------------------------------
// Pass 2: 512 threads, 16x8x4 tile. Value rows rebuilt into dynamic smem at
// PADDED stride 10 floats (40 B, 8B-aligned): divergent row reads are
// 4 x LDS.64 + 1 x LDS.32 (5 smem ops/row instead of 9 -> ~45% fewer
// wavefronts on the dominant gather). Self-row neighbors (code 0x15) use a
// register-computed s_self (bit-identical) and skip their 9 loads.
// ---------------------------------------------------------------------------
__global__ __launch_bounds__(512) void pass2_kernel(const float* __restrict__ anat,
                                                    const float* __restrict__ ksig,
                                                    float* __restrict__ out) {
    extern __shared__ __align__(16) float smem_dyn[];
    float* s9  = smem_dyn;                     // H2ROWS * ROWP, reused for out staging
    float* s_a = smem_dyn + H2ROWS * ROWP;     // A2ROWS

    int tid = threadIdx.x;
    int lx = tid & 15, ly = (tid >> 4) & 7, lz = tid >> 7;
    int x0 = blockIdx.x * 16, y0 = blockIdx.y * 8, z0 = blockIdx.z * 4;

    // anat halo 20x12x8 (offset -2).
    for (int t = tid; t < A2ROWS; t += 512) {
        int ax = t % A2X; int r = t / A2X; int ay = r % 12; int az = r / 12;
        int gx = (x0 + ax + 126) & 127;
        int gy = (y0 + ay + 126) & 127;
        int gz = (z0 + az + 62) & 63;
        s_a[t] = __ldg(&anat[(gz << 14) | (gy << 7) | gx]);
    }

    int i = ((z0 + lz) << 14) | ((y0 + ly) << 7) | (x0 + lx);
    uint4 cwv = g_code4[i];
    unsigned cw[3] = { cwv.x, cwv.y, cwv.z };
    float ks = __ldg(&ksig[0]);
    __syncthreads();

    // Rebuild the 1080 value rows (decode 9 codes, gather from s_a), store
    // as 4 x STS.64 + 1 x STS.32 at stride ROWP.
    for (int row = tid; row < H2ROWS; row += 512) {
        int hx = row % H2X; int r = row / H2X; int hy = r % 10; int hz = r / 10;
        int gx = (x0 + hx + 127) & 127;
        int gy = (y0 + hy + 127) & 127;
        int gz = (z0 + hz + 63) & 63;
        uint4 w = g_code4[(gz << 14) | (gy << 7) | gx];
        unsigned ws[3] = { w.x, w.y, w.z };
        int ac = (hz + 1) * A2XY + (hy + 1) * A2X + (hx + 1) - (A2XY + A2X + 1);
        float v[9];
#pragma unroll
        for (int t = 0; t < 9; ++t) {
            unsigned c = (ws[t >> 2] >> ((t & 3) * 8)) & 0xffu;
            int off = (int)(c >> 4) * A2XY + (int)((c >> 2) & 3) * A2X + (int)(c & 3);
            v[t] = s_a[ac + off];
        }
        float2* d2 = (float2*)&s9[row * ROWP];
        d2[0] = make_float2(v[0], v[1]);
        d2[1] = make_float2(v[2], v[3]);
        d2[2] = make_float2(v[4], v[5]);
        d2[3] = make_float2(v[6], v[7]);
        s9[row * ROWP + 8] = v[8];
    }
    __syncthreads();

    int center = (lz + 1) * H2XY + (ly + 1) * H2X + (lx + 1) - (H2XY + H2X + 1);
    int ownrow = center + (H2XY + H2X + 1);
    float wi[KNN];
    {
        const float2* o2 = (const float2*)&s9[ownrow * ROWP];
        float2 a = o2[0], b = o2[1], c2 = o2[2], d = o2[3];
        wi[0] = a.x; wi[1] = a.y; wi[2] = b.x; wi[3] = b.y;
        wi[4] = c2.x; wi[5] = c2.y; wi[6] = d.x; wi[7] = d.y;
        wi[8] = s9[ownrow * ROWP + 8];
    }

    // sigma = std(Wk, ddof=1), two-pass for fp32 stability
    float sum = 0.f;
#pragma unroll
    for (int t = 0; t < KNN; ++t) sum += wi[t];
    float mean = sum * (1.0f / 9.0f);
    float var = 0.f;
#pragma unroll
    for (int t = 0; t < KNN; ++t) { float d = wi[t] - mean; var += d * d; }
    var *= (1.0f / 8.0f);
    float sigma = sqrtf(var);
    bool  zeroSig = (sigma == 0.0f);
    float sig = zeroSig ? 1.0f : sigma;

    // logits = -(||diff|| / sigma / (sqrt(2)*ks))^2 = -s / (2*sigma^2*ks^2)
    float inv = 1.0f / (2.0f * sig * sig * ks * ks);

    float wie[KNN];
#pragma unroll
    for (int t = 0; t < KNN; ++t) wie[t] = wi[t] + 1e-6f;

    // Self-distance (bit-identical to general path when neighbor row == own row)
    float s_self = 0.f;
#pragma unroll
    for (int t = 0; t < KNN; ++t) {
        float df = wie[t] - wi[t];
        s_self = fmaf(df, df, s_self);
    }

    float logits[KNN];
#pragma unroll
    for (int j = 0; j < KNN; ++j) {
        int c = (int)((cw[j >> 2] >> ((j & 3) * 8)) & 0xffu);
        float s;
        if (c == 0x15) {
            s = s_self;
        } else {
            int rowc = center + (c >> 4) * H2XY + ((c >> 2) & 3) * H2X + (c & 3);
            const float2* nr2 = (const float2*)&s9[rowc * ROWP];
            float2 p0 = nr2[0], p1 = nr2[1], p2 = nr2[2], p3 = nr2[3];
            float p8 = s9[rowc * ROWP + 8];
            float d0 = wie[0] - p0.x, d1 = wie[1] - p0.y;
            float d2 = wie[2] - p1.x, d3 = wie[3] - p1.y;
            float d4 = wie[4] - p2.x, d5 = wie[5] - p2.y;
            float d6 = wie[6] - p3.x, d7 = wie[7] - p3.y;
            float d8 = wie[8] - p8;
            s = d0 * d0;
            s = fmaf(d1, d1, s); s = fmaf(d2, d2, s);
            s = fmaf(d3, d3, s); s = fmaf(d4, d4, s);
            s = fmaf(d5, d5, s); s = fmaf(d6, d6, s);
            s = fmaf(d7, d7, s); s = fmaf(d8, d8, s);
        }
        logits[j] = zeroSig ? 0.0f : -(s * inv);
    }

    // softmax over the 9 neighbors
    float mx = logits[0];
#pragma unroll
    for (int j = 1; j < KNN; ++j) mx = fmaxf(mx, logits[j]);
    float e[KNN], se = 0.f;
#pragma unroll
    for (int j = 0; j < KNN; ++j) { e[j] = __expf(logits[j] - mx); se += e[j]; }
    float rse = 1.0f / se;

    __syncthreads();                       // all s9 reads done; reuse buffer
#pragma unroll
    for (int j = 0; j < KNN; ++j) s9[tid * KNN + j] = e[j] * rse;
    __syncthreads();

    // Coalesced out: 32 lines x 144 floats = 36 float4 per line, 1152 total.
    float4* s_out4 = (float4*)s9;
    for (int q = tid; q < 1152; q += 512) {
        int line = q / 36, off = q - line * 36;
        int llz = line >> 3, lly = line & 7;
        int vox = ((z0 + llz) << 14) | ((y0 + lly) << 7) | x0;
        ((float4*)(out + (size_t)vox * KNN))[off] = s_out4[q];
    }
}

extern "C" void kernel_launch(void* const* d_in, const int* in_sizes, int n_in,
                              void* d_out, int out_size) {
    const float* anat = (const float*)d_in[0];
    const float* ksig = (const float*)d_in[1];
    float* out = (float*)d_out;

    dim3 grid1(128 / TX, 128 / TY, 64 / TZ);    // 4096 blocks
    pass1_kernel<<<grid1, 256>>>(anat);

    cudaFuncSetAttribute(pass2_kernel, cudaFuncAttributeMaxDynamicSharedMemorySize,
                         SMEM2_BYTES);
    dim3 grid2(128 / 16, 128 / 8, 64 / 4);      // 8 x 16 x 16 = 2048 blocks
    pass2_kernel<<<grid2, 512, SMEM2_BYTES>>>(anat, ksig, out);
}

// round 16
// speedup vs baseline: 1.0266x; 1.0266x over previous
#include <cuda_runtime.h>

// Problem constants: H=64, M=N=128, k=9, w=3
#define PTOT (64 * 128 * 128)
#define KNN  9

// ---- pass1 tile: 16 x 4 x 4; halo 18 x 6 x 6 ----
#define TX 16
#define TY 4
#define TZ 4
#define HX 18
#define HY 6
#define HROWS (HX * HY * 6)     // 648
#define HXY (HX * HY)           // 108

// ---- pass2 tile: 16 x 8 x 4, 512 threads; value-row halo 18 x 10 x 6 ----
#define H2X 18
#define H2XY (18 * 10)          // 180
#define H2ROWS (18 * 10 * 6)    // 1080
#define ROWP 10                 // padded row width (floats): 40 B, 8B-aligned
// pass2 anat halo: 20 x 12 x 8
#define A2X 20
#define A2XY 240
#define A2ROWS (A2X * 12 * 8)   // 1920
#define SMEM2_BYTES ((H2ROWS * ROWP + A2ROWS) * 4)  // 43200 + 7680 = 50880 B

// Scratch: ONLY codes — one uint4 per voxel, 9 code bytes in .x/.y/.z
// (byte = (oz<<4)|(oy<<2)|ox, offsets in 0..2), .w unused. 16.8 MB.
__device__ uint4 g_code4[PTOT];

// ---------------------------------------------------------------------------
// Pass 1 (exact R14 version — measured ~62us): stable top-9 of 27 periodic
// window neighbors by |v - center| via branchless byte-packed rank counting.
//   rank(c) = #{j<c: d_j <= d_c} + #{j>c: d_j < d_c}
// Pre-add the c-side at compile time (init_c = c); runtime per pair:
//   p = sign(bits(d_c) - bits(d_j));  rank_j += p*Wj;  rank_c -= p*Wc
// Integer compares on abs-bit patterns (order == float order for d >= 0);
// center candidate 13 folded into init / literal-zero compares.
// ---------------------------------------------------------------------------
__global__ __launch_bounds__(256) void pass1_kernel(const float* __restrict__ anat) {
    __shared__ float s_anat[HROWS];
    __shared__ unsigned char s_cb[256 * 20];

    int tid = threadIdx.x;
    int lx = tid & 15, ly = (tid >> 4) & 3, lz = tid >> 6;
    int x0 = blockIdx.x * TX, y0 = blockIdx.y * TY, z0 = blockIdx.z * TZ;

    for (int t = tid; t < HROWS; t += 256) {
        int hx = t % HX; int r = t / HX; int hy = r % HY; int hz = r / HY;
        int gx = (x0 + hx + 127) & 127;
        int gy = (y0 + hy + 127) & 127;
        int gz = (z0 + hz + 63) & 63;
        s_anat[t] = __ldg(&anat[(gz << 14) | (gy << 7) | gx]);
    }
    __syncthreads();

    int center = (lz + 1) * HXY + (ly + 1) * HX + (lx + 1);
    float ac = s_anat[center];

    int di[27];
#pragma unroll
    for (int oz = 0; oz < 3; ++oz)
#pragma unroll
        for (int oy = 0; oy < 3; ++oy)
#pragma unroll
            for (int ox = 0; ox < 3; ++ox) {
                int c = oz * 9 + oy * 3 + ox;
                float v = s_anat[center + (oz - 1) * HXY + (oy - 1) * HX + (ox - 1)];
                di[c] = (int)(__float_as_uint(v - ac) & 0x7fffffffu);
            }

    unsigned ri[7] = { 0x03020100u, 0x07060504u, 0x0B0A0908u, 0x0F0E0D0Cu,
                       0x13121110u, 0x17161514u, 0x001A1918u };

#pragma unroll
    for (int j = 0; j < 13; ++j) {
        unsigned p = ((unsigned)(-di[j])) >> 31;
        ri[j >> 2] += p * (1u << ((j & 3) * 8));
        ri[3]      -= p * (1u << 8);
    }

#pragma unroll
    for (int o = 1; o < 27; ++o)
#pragma unroll
        for (int j = 0; j + o < 27; ++j) {
            const int c = j + o;
            if (j == 13 || c == 13) continue;
            unsigned p = ((unsigned)(di[c] - di[j])) >> 31;   // d_j > d_c
            ri[j >> 2] += p * (1u << ((j & 3) * 8));
            ri[c >> 2] -= p * (1u << ((c & 3) * 8));
        }

    unsigned char* myrow = &s_cb[tid * 20];
#pragma unroll
    for (int c = 0; c < 27; ++c) {
        int r = (int)((ri[c >> 2] >> ((c & 3) * 8)) & 255u);
        if (r < KNN) {
            int oz = c / 9, rem = c - 9 * oz, oy = rem / 3, ox = rem - 3 * oy; // compile-time
            myrow[r] = (unsigned char)((oz << 4) | (oy << 2) | ox);
        }
    }
    unsigned w0 = *(const unsigned*)&myrow[0];
    unsigned w1 = *(const unsigned*)&myrow[4];
    unsigned w2 = (unsigned)myrow[8];
    int i = ((z0 + lz) << 14) | ((y0 + ly) << 7) | (x0 + lx);
    g_code4[i] = make_uint4(w0, w1, w2, 0u);
}

// ---------------------------------------------------------------------------
// Pass 2: 512 threads, 16x8x4 tile, __launch_bounds__(512,4) -> <=32 regs so
// 4 blocks (64 warps) stay resident. Value rows rebuilt into dynamic smem at
// padded stride 10 floats (40 B, 8B-aligned): each divergent row read is
// 4 x LDS.64 + 1 x LDS.32 (5 smem ops instead of 9 -> ~45% fewer wavefronts
// on the dominant gather). No branches in the logits loop (register-lean).
// ---------------------------------------------------------------------------
__global__ __launch_bounds__(512, 4) void pass2_kernel(const float* __restrict__ anat,
                                                       const float* __restrict__ ksig,
                                                       float* __restrict__ out) {
    extern __shared__ __align__(16) float smem_dyn[];
    float* s9  = smem_dyn;                     // H2ROWS * ROWP, reused for out staging
    float* s_a = smem_dyn + H2ROWS * ROWP;     // A2ROWS

    int tid = threadIdx.x;
    int lx = tid & 15, ly = (tid >> 4) & 7, lz = tid >> 7;
    int x0 = blockIdx.x * 16, y0 = blockIdx.y * 8, z0 = blockIdx.z * 4;

    // anat halo 20x12x8 (offset -2).
    for (int t = tid; t < A2ROWS; t += 512) {
        int ax = t % A2X; int r = t / A2X; int ay = r % 12; int az = r / 12;
        int gx = (x0 + ax + 126) & 127;
        int gy = (y0 + ay + 126) & 127;
        int gz = (z0 + az + 62) & 63;
        s_a[t] = __ldg(&anat[(gz << 14) | (gy << 7) | gx]);
    }

    int i = ((z0 + lz) << 14) | ((y0 + ly) << 7) | (x0 + lx);
    uint4 cwv = g_code4[i];
    unsigned cw[3] = { cwv.x, cwv.y, cwv.z };
    float ks = __ldg(&ksig[0]);
    __syncthreads();

    // Rebuild the 1080 value rows (decode 9 codes, gather from s_a); store
    // as 4 x STS.64 + 1 x STS.32 at stride ROWP.
    for (int row = tid; row < H2ROWS; row += 512) {
        int hx = row % H2X; int r = row / H2X; int hy = r % 10; int hz = r / 10;
        int gx = (x0 + hx + 127) & 127;
        int gy = (y0 + hy + 127) & 127;
        int gz = (z0 + hz + 63) & 63;
        uint4 w = g_code4[(gz << 14) | (gy << 7) | gx];
        unsigned ws[3] = { w.x, w.y, w.z };
        int ac = (hz + 1) * A2XY + (hy + 1) * A2X + (hx + 1) - (A2XY + A2X + 1);
        float v[9];
#pragma unroll
        for (int t = 0; t < 9; ++t) {
            unsigned c = (ws[t >> 2] >> ((t & 3) * 8)) & 0xffu;
            int off = (int)(c >> 4) * A2XY + (int)((c >> 2) & 3) * A2X + (int)(c & 3);
            v[t] = s_a[ac + off];
        }
        float2* d2 = (float2*)&s9[row * ROWP];
        d2[0] = make_float2(v[0], v[1]);
        d2[1] = make_float2(v[2], v[3]);
        d2[2] = make_float2(v[4], v[5]);
        d2[3] = make_float2(v[6], v[7]);
        s9[row * ROWP + 8] = v[8];
    }
    __syncthreads();

    int center = (lz + 1) * H2XY + (ly + 1) * H2X + (lx + 1) - (H2XY + H2X + 1);
    int ownrow = center + (H2XY + H2X + 1);
    float wi[KNN];
    {
        const float2* o2 = (const float2*)&s9[ownrow * ROWP];
        float2 a = o2[0], b = o2[1], c2 = o2[2], d = o2[3];
        wi[0] = a.x; wi[1] = a.y; wi[2] = b.x; wi[3] = b.y;
        wi[4] = c2.x; wi[5] = c2.y; wi[6] = d.x; wi[7] = d.y;
        wi[8] = s9[ownrow * ROWP + 8];
    }

    // sigma = std(Wk, ddof=1), two-pass for fp32 stability
    float sum = 0.f;
#pragma unroll
    for (int t = 0; t < KNN; ++t) sum += wi[t];
    float mean = sum * (1.0f / 9.0f);
    float var = 0.f;
#pragma unroll
    for (int t = 0; t < KNN; ++t) { float d = wi[t] - mean; var += d * d; }
    var *= (1.0f / 8.0f);
    float sigma = sqrtf(var);
    bool  zeroSig = (sigma == 0.0f);
    float sig = zeroSig ? 1.0f : sigma;

    // logits = -(||diff|| / sigma / (sqrt(2)*ks))^2 = -s / (2*sigma^2*ks^2)
    float inv = 1.0f / (2.0f * sig * sig * ks * ks);

    // overwrite wi in place with wie = wi + 1e-6 (wi dead after this point)
#pragma unroll
    for (int t = 0; t < KNN; ++t) wi[t] += 1e-6f;

    float logits[KNN];
#pragma unroll
    for (int j = 0; j < KNN; ++j) {
        int c = (int)((cw[j >> 2] >> ((j & 3) * 8)) & 0xffu);
        int rowc = center + (c >> 4) * H2XY + ((c >> 2) & 3) * H2X + (c & 3);
        const float2* nr2 = (const float2*)&s9[rowc * ROWP];
        float2 p0 = nr2[0], p1 = nr2[1], p2 = nr2[2], p3 = nr2[3];
        float p8 = s9[rowc * ROWP + 8];
        float d0 = wi[0] - p0.x, d1 = wi[1] - p0.y;
        float d2 = wi[2] - p1.x, d3 = wi[3] - p1.y;
        float d4 = wi[4] - p2.x, d5 = wi[5] - p2.y;
        float d6 = wi[6] - p3.x, d7 = wi[7] - p3.y;
        float d8 = wi[8] - p8;
        float s = d0 * d0;
        s = fmaf(d1, d1, s); s = fmaf(d2, d2, s);
        s = fmaf(d3, d3, s); s = fmaf(d4, d4, s);
        s = fmaf(d5, d5, s); s = fmaf(d6, d6, s);
        s = fmaf(d7, d7, s); s = fmaf(d8, d8, s);
        logits[j] = zeroSig ? 0.0f : -(s * inv);
    }

    // softmax over the 9 neighbors
    float mx = logits[0];
#pragma unroll
    for (int j = 1; j < KNN; ++j) mx = fmaxf(mx, logits[j]);
    float e[KNN], se = 0.f;
#pragma unroll
    for (int j = 0; j < KNN; ++j) { e[j] = __expf(logits[j] - mx); se += e[j]; }
    float rse = 1.0f / se;

    __syncthreads();                       // all s9 reads done; reuse buffer
#pragma unroll
    for (int j = 0; j < KNN; ++j) s9[tid * KNN + j] = e[j] * rse;
    __syncthreads();

    // Coalesced out: 32 lines x 144 floats = 36 float4 per line, 1152 total.
    float4* s_out4 = (float4*)s9;
    for (int q = tid; q < 1152; q += 512) {
        int line = q / 36, off = q - line * 36;
        int llz = line >> 3, lly = line & 7;
        int vox = ((z0 + llz) << 14) | ((y0 + lly) << 7) | x0;
        ((float4*)(out + (size_t)vox * KNN))[off] = s_out4[q];
    }
}

extern "C" void kernel_launch(void* const* d_in, const int* in_sizes, int n_in,
                              void* d_out, int out_size) {
    const float* anat = (const float*)d_in[0];
    const float* ksig = (const float*)d_in[1];
    float* out = (float*)d_out;

    dim3 grid1(128 / TX, 128 / TY, 64 / TZ);    // 4096 blocks
    pass1_kernel<<<grid1, 256>>>(anat);

    cudaFuncSetAttribute(pass2_kernel, cudaFuncAttributeMaxDynamicSharedMemorySize,
                         SMEM2_BYTES);
    dim3 grid2(128 / 16, 128 / 8, 64 / 4);      // 8 x 16 x 16 = 2048 blocks
    pass2_kernel<<<grid2, 512, SMEM2_BYTES>>>(anat, ksig, out);
}

// round 17
// speedup vs baseline: 1.0747x; 1.0468x over previous
#include <cuda_runtime.h>

// Problem constants: H=64, M=N=128, k=9, w=3
#define PTOT (64 * 128 * 128)
#define KNN  9

// ---- pass1 tile: 16 x 4 x 4; halo 18 x 6 x 6 ----
#define TX 16
#define TY 4
#define TZ 4
#define HX 18
#define HY 6
#define HROWS (HX * HY * 6)     // 648
#define HXY (HX * HY)           // 108

// ---- pass2 tile: 16 x 8 x 4, 512 threads; value-row halo 18 x 10 x 6 ----
#define TY2 8
#define H2X 18
#define H2XY (18 * 10)          // 180
#define H2ROWS (18 * 10 * 6)    // 1080
// pass2 anat halo: 20 x 12 x 8
#define A2X 20
#define A2XY 240
#define A2ROWS (A2X * 12 * 8)   // 1920

// Scratch: ONLY codes — one uint4 per voxel, 9 code bytes in .x/.y/.z
// (byte = (oz<<4)|(oy<<2)|ox, offsets in 0..2), .w unused. 16.8 MB.
__device__ uint4 g_code4[PTOT];

// ---------------------------------------------------------------------------
// Pass 1 (exact R14 version — measured 62.3us, best of 6 variants):
// stable top-9 of 27 periodic window neighbors by |v - center| via
// branchless byte-packed rank counting.
//   rank(c) = #{j<c: d_j <= d_c} + #{j>c: d_j < d_c}
// Pre-add the c-side of every pair at compile time (init_c = c); per pair:
//   p = sign(bits(d_c) - bits(d_j));  rank_j += p*Wj;  rank_c -= p*Wc
// Integer compares on abs-bit patterns (order == float order for d >= 0);
// center candidate 13 (d == 0) folded into init / literal-zero compares.
// Epilogue: private 20B smem rows (gcd(5,32)=1, conflict-free predicated
// byte-STS), own-row readback without a barrier, coalesced uint4 store.
// ---------------------------------------------------------------------------
__global__ __launch_bounds__(256) void pass1_kernel(const float* __restrict__ anat) {
    __shared__ float s_anat[HROWS];
    __shared__ unsigned char s_cb[256 * 20];

    int tid = threadIdx.x;
    int lx = tid & 15, ly = (tid >> 4) & 3, lz = tid >> 6;
    int x0 = blockIdx.x * TX, y0 = blockIdx.y * TY, z0 = blockIdx.z * TZ;

    for (int t = tid; t < HROWS; t += 256) {
        int hx = t % HX; int r = t / HX; int hy = r % HY; int hz = r / HY;
        int gx = (x0 + hx + 127) & 127;
        int gy = (y0 + hy + 127) & 127;
        int gz = (z0 + hz + 63) & 63;
        s_anat[t] = __ldg(&anat[(gz << 14) | (gy << 7) | gx]);
    }
    __syncthreads();

    int center = (lz + 1) * HXY + (ly + 1) * HX + (lx + 1);
    float ac = s_anat[center];

    int di[27];
#pragma unroll
    for (int oz = 0; oz < 3; ++oz)
#pragma unroll
        for (int oy = 0; oy < 3; ++oy)
#pragma unroll
            for (int ox = 0; ox < 3; ++ox) {
                int c = oz * 9 + oy * 3 + ox;
                float v = s_anat[center + (oz - 1) * HXY + (oy - 1) * HX + (ox - 1)];
                di[c] = (int)(__float_as_uint(v - ac) & 0x7fffffffu);
            }

    unsigned ri[7] = { 0x03020100u, 0x07060504u, 0x0B0A0908u, 0x0F0E0D0Cu,
                       0x13121110u, 0x17161514u, 0x001A1918u };

#pragma unroll
    for (int j = 0; j < 13; ++j) {
        unsigned p = ((unsigned)(-di[j])) >> 31;
        ri[j >> 2] += p * (1u << ((j & 3) * 8));
        ri[3]      -= p * (1u << 8);
    }

#pragma unroll
    for (int o = 1; o < 27; ++o)
#pragma unroll
        for (int j = 0; j + o < 27; ++j) {
            const int c = j + o;
            if (j == 13 || c == 13) continue;
            unsigned p = ((unsigned)(di[c] - di[j])) >> 31;   // d_j > d_c
            ri[j >> 2] += p * (1u << ((j & 3) * 8));
            ri[c >> 2] -= p * (1u << ((c & 3) * 8));
        }

    unsigned char* myrow = &s_cb[tid * 20];
#pragma unroll
    for (int c = 0; c < 27; ++c) {
        int r = (int)((ri[c >> 2] >> ((c & 3) * 8)) & 255u);
        if (r < KNN) {
            int oz = c / 9, rem = c - 9 * oz, oy = rem / 3, ox = rem - 3 * oy; // compile-time
            myrow[r] = (unsigned char)((oz << 4) | (oy << 2) | ox);
        }
    }
    unsigned w0 = *(const unsigned*)&myrow[0];
    unsigned w1 = *(const unsigned*)&myrow[4];
    unsigned w2 = (unsigned)myrow[8];
    int i = ((z0 + lz) << 14) | ((y0 + ly) << 7) | (x0 + lx);
    g_code4[i] = make_uint4(w0, w1, w2, 0u);
}

// ---------------------------------------------------------------------------
// Pass 2 (exact R13 version — measured 52.3us, best of 9 variants):
// 512 threads, 16x8x4 tile. Rebuild the 1080 value rows in static smem at
// SCALAR stride 9 (gcd(9,32)=1 -> data-divergent row reads near
// conflict-free; LDS.32 bank period 32 beats any vector width) from a
// 20x12x8 anat halo + one LDG.128 of codes per row. 46.6 KB smem,
// 4 blocks/SM = 64 warps. Output staged through s9, written back as float4.
// ---------------------------------------------------------------------------
__global__ __launch_bounds__(512) void pass2_kernel(const float* __restrict__ anat,
                                                    const float* __restrict__ ksig,
                                                    float* __restrict__ out) {
    __shared__ __align__(16) float s9[H2ROWS * 9];  // 38880 B, reused for out staging
    __shared__ float s_a[A2ROWS];                   // 7680 B anat halo

    int tid = threadIdx.x;
    int lx = tid & 15, ly = (tid >> 4) & 7, lz = tid >> 7;
    int x0 = blockIdx.x * TX, y0 = blockIdx.y * TY2, z0 = blockIdx.z * TZ;

    // anat halo 20x12x8 (offset -2).
    for (int t = tid; t < A2ROWS; t += 512) {
        int ax = t % A2X; int r = t / A2X; int ay = r % 12; int az = r / 12;
        int gx = (x0 + ax + 126) & 127;
        int gy = (y0 + ay + 126) & 127;
        int gz = (z0 + az + 62) & 63;
        s_a[t] = __ldg(&anat[(gz << 14) | (gy << 7) | gx]);
    }

    int i = ((z0 + lz) << 14) | ((y0 + ly) << 7) | (x0 + lx);
    uint4 cwv = g_code4[i];
    unsigned cw[3] = { cwv.x, cwv.y, cwv.z };
    float ks = __ldg(&ksig[0]);
    __syncthreads();

    // Build the 1080 value rows: decode 9 codes per row, gather from s_a.
    for (int row = tid; row < H2ROWS; row += 512) {
        int hx = row % H2X; int r = row / H2X; int hy = r % 10; int hz = r / 10;
        int gx = (x0 + hx + 127) & 127;
        int gy = (y0 + hy + 127) & 127;
        int gz = (z0 + hz + 63) & 63;
        uint4 w = g_code4[(gz << 14) | (gy << 7) | gx];
        unsigned ws[3] = { w.x, w.y, w.z };
        // row (hx,hy,hz) sits at anat-halo coords (hx+1,hy+1,hz+1); code
        // offsets are (oz-1,oy-1,ox-1) -> pre-subtract.
        int ac = (hz + 1) * A2XY + (hy + 1) * A2X + (hx + 1) - (A2XY + A2X + 1);
        float* d = &s9[row * 9];
#pragma unroll
        for (int t = 0; t < 9; ++t) {
            unsigned c = (ws[t >> 2] >> ((t & 3) * 8)) & 0xffu;
            int off = (int)(c >> 4) * A2XY + (int)((c >> 2) & 3) * A2X + (int)(c & 3);
            d[t] = s_a[ac + off];
        }
    }
    __syncthreads();

    int center = (lz + 1) * H2XY + (ly + 1) * H2X + (lx + 1) - (H2XY + H2X + 1);
    float wi[KNN];
#pragma unroll
    for (int t = 0; t < KNN; ++t) wi[t] = s9[(center + (H2XY + H2X + 1)) * 9 + t];

    // sigma = std(Wk, ddof=1), two-pass for fp32 stability
    float sum = 0.f;
#pragma unroll
    for (int t = 0; t < KNN; ++t) sum += wi[t];
    float mean = sum * (1.0f / 9.0f);
    float var = 0.f;
#pragma unroll
    for (int t = 0; t < KNN; ++t) { float d = wi[t] - mean; var += d * d; }
    var *= (1.0f / 8.0f);
    float sigma = sqrtf(var);
    bool  zeroSig = (sigma == 0.0f);
    float sig = zeroSig ? 1.0f : sigma;

    // logits = -(||diff|| / sigma / (sqrt(2)*ks))^2 = -s / (2*sigma^2*ks^2)
    float inv = 1.0f / (2.0f * sig * sig * ks * ks);

    float wie[KNN];
#pragma unroll
    for (int t = 0; t < KNN; ++t) wie[t] = wi[t] + 1e-6f;

    float logits[KNN];
#pragma unroll
    for (int j = 0; j < KNN; ++j) {
        int c = (int)((cw[j >> 2] >> ((j & 3) * 8)) & 0xffu);
        int rowc = center + (c >> 4) * H2XY + ((c >> 2) & 3) * H2X + (c & 3);
        const float* nr = &s9[rowc * 9];
        float s = 0.f;
#pragma unroll
        for (int t = 0; t < KNN; ++t) {
            float df = wie[t] - nr[t];
            s = fmaf(df, df, s);
        }
        logits[j] = zeroSig ? 0.0f : -(s * inv);
    }

    // softmax over the 9 neighbors
    float mx = logits[0];
#pragma unroll
    for (int j = 1; j < KNN; ++j) mx = fmaxf(mx, logits[j]);
    float e[KNN], se = 0.f;
#pragma unroll
    for (int j = 0; j < KNN; ++j) { e[j] = __expf(logits[j] - mx); se += e[j]; }
    float rse = 1.0f / se;

    __syncthreads();                       // all s9 reads done; reuse buffer
#pragma unroll
    for (int j = 0; j < KNN; ++j) s9[tid * KNN + j] = e[j] * rse;
    __syncthreads();

    // Coalesced out: 32 lines x 144 floats = 36 float4 per line, 1152 total.
    float4* s_out4 = (float4*)s9;
    for (int q = tid; q < 1152; q += 512) {
        int line = q / 36, off = q - line * 36;
        int llz = line >> 3, lly = line & 7;
        int vox = ((z0 + llz) << 14) | ((y0 + lly) << 7) | x0;
        ((float4*)(out + (size_t)vox * KNN))[off] = s_out4[q];
    }
}

extern "C" void kernel_launch(void* const* d_in, const int* in_sizes, int n_in,
                              void* d_out, int out_size) {
    const float* anat = (const float*)d_in[0];
    const float* ksig = (const float*)d_in[1];
    float* out = (float*)d_out;

    dim3 grid1(128 / TX, 128 / TY, 64 / TZ);    // 4096 blocks
    pass1_kernel<<<grid1, 256>>>(anat);
    dim3 grid2(128 / TX, 128 / TY2, 64 / TZ);   // 8 x 16 x 16 = 2048 blocks
    pass2_kernel<<<grid2, 512>>>(anat, ksig, out);
}